// round 1
// baseline (speedup 1.0000x reference)
#include <cuda_runtime.h>

#define NHID 32

// Folded constants: per hidden unit j, 9 feature coefficients (basis
// {1,c0,s0}x{1,c1,s1}, b1 folded into the constant term), then W2[j][0..1], pad.
__device__ float g_const[NHID * 12];

struct cpx { float x, y; };

__device__ void apply1q(cpx* s, cpx m00, cpx m01, cpx m10, cpx m11, int wire)
{
    int st = 1 << (2 - wire);
    for (int i = 0; i < 8; i++) {
        if (i & st) continue;
        cpx a = s[i], b = s[i + st];
        cpx n0 = { m00.x*a.x - m00.y*a.y + m01.x*b.x - m01.y*b.y,
                   m00.x*a.y + m00.y*a.x + m01.x*b.y + m01.y*b.x };
        cpx n1 = { m10.x*a.x - m10.y*a.y + m11.x*b.x - m11.y*b.y,
                   m10.x*a.y + m10.y*a.x + m11.x*b.y + m11.y*b.x };
        s[i] = n0; s[i + st] = n1;
    }
}

__device__ void applyCRX(cpx* s, float half_t_c, float half_t_s, int ctrl, int tgt)
{
    // RX(t) on tgt where ctrl bit == 1.  RX = [[c, -i s],[-i s, c]]
    int cs = 1 << (2 - ctrl), ts = 1 << (2 - tgt);
    float c = half_t_c, sn = half_t_s;
    for (int i = 0; i < 8; i++) {
        if (!(i & cs) || (i & ts)) continue;
        cpx a = s[i], b = s[i + ts];
        s[i]      = { c*a.x + sn*b.y, c*a.y - sn*b.x };
        s[i + ts] = { c*b.x + sn*a.y, c*b.y - sn*a.x };
    }
}

// One launch per kernel_launch call; 32 threads, thread j builds row j of the
// folded coefficient table. Cost is negligible (8 gates on 8 amplitudes).
__global__ void setup_kernel(const float* __restrict__ theta,
                             const float* __restrict__ W1,
                             const float* __restrict__ b1,
                             const float* __restrict__ W2)
{
    int j = threadIdx.x;
    if (j >= NHID) return;

    // Columns of the fixed unitary acting on the 4 reachable basis states
    // |i j 0>  (indices 0,2,4,6). For a>=2 fold the -i from RX(x0)|0>.
    cpx V[4][8];
    for (int a = 0; a < 4; a++) {
        cpx s[8];
        for (int i = 0; i < 8; i++) s[i] = {0.f, 0.f};
        s[a * 2] = {1.f, 0.f};
        float c, sn;
        sincosf(0.5f * theta[0], &sn, &c);
        apply1q(s, {c,0.f},{0.f,-sn},{0.f,-sn},{c,0.f}, 0);     // RX w0
        sincosf(0.5f * theta[1], &sn, &c);
        apply1q(s, {c,0.f},{-sn,0.f},{sn,0.f},{c,0.f}, 1);      // RY w1
        sincosf(0.5f * theta[2], &sn, &c);
        apply1q(s, {c,-sn},{0.f,0.f},{0.f,0.f},{c,sn}, 2);      // RZ w2
        sincosf(0.5f * theta[3], &sn, &c);
        applyCRX(s, c, sn, 0, 1);                                // CRX(ctrl0,tgt1)
        sincosf(0.5f * theta[4], &sn, &c);
        apply1q(s, {c,0.f},{-sn,0.f},{sn,0.f},{c,0.f}, 2);      // RY w2
        sincosf(0.5f * theta[5], &sn, &c);
        apply1q(s, {c,0.f},{0.f,-sn},{0.f,-sn},{c,0.f}, 1);     // RX w1
        sincosf(0.5f * theta[6], &sn, &c);
        applyCRX(s, c, sn, 1, 2);                                // CRX(ctrl1,tgt2)
        sincosf(0.5f * theta[7], &sn, &c);
        apply1q(s, {c,-sn},{0.f,0.f},{0.f,0.f},{c,sn}, 0);      // RZ w0
        for (int k = 0; k < 8; k++)
            V[a][k] = (a >= 2) ? cpx{ s[k].y, -s[k].x } : s[k]; // * (-i)
    }

    // M[a][b] = sum_k W1[k,j] * Re(V_a[k] conj(V_b[k]))
    float M[4][4];
    for (int a = 0; a < 4; a++)
        for (int b = 0; b < 4; b++) {
            float m = 0.f;
            for (int k = 0; k < 8; k++)
                m += W1[k * NHID + j] * (V[a][k].x * V[b][k].x + V[a][k].y * V[b][k].y);
            M[a][b] = m;
        }

    // Half-angle product tables over basis (1, cos, sin):
    //  p^2=(1+c)/2, pq=s/2, q^2=(1-c)/2
    const float R[2][2][3] = { { {0.5f, 0.5f, 0.f}, {0.f, 0.f, 0.5f} },
                               { {0.f, 0.f, 0.5f}, {0.5f, -0.5f, 0.f} } };
    float K[3][3] = { {0.f,0.f,0.f},{0.f,0.f,0.f},{0.f,0.f,0.f} };
    for (int a = 0; a < 4; a++)
        for (int b = 0; b < 4; b++) {
            int ia = a >> 1, ja = a & 1, ib = b >> 1, jb = b & 1;
            float Mab = M[a][b];
            for (int m = 0; m < 3; m++)
                for (int n = 0; n < 3; n++)
                    K[m][n] += Mab * R[ia][ib][m] * R[ja][jb][n];
        }
    K[0][0] += b1[j];

    for (int t = 0; t < 9; t++) g_const[j * 12 + t] = K[t / 3][t % 3];
    g_const[j * 12 + 9]  = W2[j * 2 + 0];
    g_const[j * 12 + 10] = W2[j * 2 + 1];
    g_const[j * 12 + 11] = 0.f;
}

// ---- packed f32x2 helpers (Blackwell FFMA2 path) ----
typedef unsigned long long u64;
__device__ __forceinline__ u64 pk2(float lo, float hi) {
    u64 r; asm("mov.b64 %0, {%1,%2};" : "=l"(r) : "f"(lo), "f"(hi)); return r;
}
__device__ __forceinline__ void upk2(u64 v, float& lo, float& hi) {
    asm("mov.b64 {%0,%1}, %2;" : "=f"(lo), "=f"(hi) : "l"(v));
}
__device__ __forceinline__ u64 ffma2(u64 a, u64 b, u64 c) {
    u64 d; asm("fma.rn.f32x2 %0, %1, %2, %3;" : "=l"(d) : "l"(a), "l"(b), "l"(c)); return d;
}
__device__ __forceinline__ u64 fmul2(u64 a, u64 b) {
    u64 d; asm("mul.rn.f32x2 %0, %1, %2;" : "=l"(d) : "l"(a), "l"(b)); return d;
}

__global__ void __launch_bounds__(256)
qmlp_kernel(const float* __restrict__ x,
            const float* __restrict__ b2,
            float* __restrict__ out, int B)
{
    // Duplicated constant layout: sd[j*24 + 2u] == sd[j*24 + 2u + 1] == const u
    // so packed (K,K) operands come straight out of LDS.128 with zero MOVs.
    __shared__ float sd[NHID * 24];
    for (int i = threadIdx.x; i < NHID * 24; i += blockDim.x)
        sd[i] = g_const[(i / 24) * 12 + (i % 24) / 2];
    __syncthreads();

    long long t  = (long long)blockIdx.x * blockDim.x + threadIdx.x;
    long long s0 = t * 4;
    if (s0 >= B) return;

    float bias0 = __ldg(&b2[0]);
    float bias1 = __ldg(&b2[1]);

    const ulonglong2* kp = reinterpret_cast<const ulonglong2*>(sd);

    if (s0 + 4 <= B) {
        // 4 samples: three coalesced LDG.128 over x[3*s0 .. 3*s0+11]
        const float4* xv = reinterpret_cast<const float4*>(x + s0 * 3);
        float4 XA = xv[0], XB = xv[1], XC = xv[2];
        // sample i uses (x0,x1); x2 is a global phase (irrelevant)
        float x0v[4] = { XA.x, XA.w, XB.z, XC.y };
        float x1v[4] = { XA.y, XB.x, XB.w, XC.z };

        float c0[4], sn0[4], c1[4], sn1[4];
        #pragma unroll
        for (int i = 0; i < 4; i++) {
            __sincosf(x0v[i], &sn0[i], &c0[i]);
            __sincosf(x1v[i], &sn1[i], &c1[i]);
        }

        // packed feature vectors: pair a = samples {0,1}, pair b = samples {2,3}
        u64 C0a = pk2(c0[0],  c0[1]),  C0b = pk2(c0[2],  c0[3]);
        u64 S0a = pk2(sn0[0], sn0[1]), S0b = pk2(sn0[2], sn0[3]);
        u64 C1a = pk2(c1[0],  c1[1]),  C1b = pk2(c1[2],  c1[3]);
        u64 S1a = pk2(sn1[0], sn1[1]), S1b = pk2(sn1[2], sn1[3]);
        u64 CCa = fmul2(C0a, C1a), CSa = fmul2(C0a, S1a);
        u64 SCa = fmul2(S0a, C1a), SSa = fmul2(S0a, S1a);
        u64 CCb = fmul2(C0b, C1b), CSb = fmul2(C0b, S1b);
        u64 SCb = fmul2(S0b, C1b), SSb = fmul2(S0b, S1b);

        u64 o0a = pk2(bias0, bias0), o1a = pk2(bias1, bias1);
        u64 o0b = o0a, o1b = o1a;

        #pragma unroll 4
        for (int j = 0; j < NHID; j++) {
            ulonglong2 q0 = kp[j*6+0], q1 = kp[j*6+1], q2 = kp[j*6+2];
            ulonglong2 q3 = kp[j*6+3], q4 = kp[j*6+4], q5 = kp[j*6+5];

            u64 ga = ffma2(C1a, q0.y, q0.x);
            ga = ffma2(S1a, q1.x, ga);
            ga = ffma2(C0a, q1.y, ga);
            ga = ffma2(CCa, q2.x, ga);
            ga = ffma2(CSa, q2.y, ga);
            ga = ffma2(S0a, q3.x, ga);
            ga = ffma2(SCa, q3.y, ga);
            ga = ffma2(SSa, q4.x, ga);

            u64 gb = ffma2(C1b, q0.y, q0.x);
            gb = ffma2(S1b, q1.x, gb);
            gb = ffma2(C0b, q1.y, gb);
            gb = ffma2(CCb, q2.x, gb);
            gb = ffma2(CSb, q2.y, gb);
            gb = ffma2(S0b, q3.x, gb);
            gb = ffma2(SCb, q3.y, gb);
            gb = ffma2(SSb, q4.x, gb);

            float la, ha, lb, hb;
            upk2(ga, la, ha);
            upk2(gb, lb, hb);
            u64 hpa = pk2(fmaxf(la, 0.f), fmaxf(ha, 0.f));
            u64 hpb = pk2(fmaxf(lb, 0.f), fmaxf(hb, 0.f));

            o0a = ffma2(hpa, q4.y, o0a);
            o1a = ffma2(hpa, q5.x, o1a);
            o0b = ffma2(hpb, q4.y, o0b);
            o1b = ffma2(hpb, q5.x, o1b);
        }

        float r00, r01, r10, r11;
        upk2(o0a, r00, r10);  // out ch0 of samples 0,1
        upk2(o1a, r01, r11);  // out ch1 of samples 0,1
        float4 w0 = { r00, r01, r10, r11 };
        upk2(o0b, r00, r10);
        upk2(o1b, r01, r11);
        float4 w1 = { r00, r01, r10, r11 };
        float4* ov = reinterpret_cast<float4*>(out + s0 * 2);
        ov[0] = w0;
        ov[1] = w1;
    } else {
        // generic scalar tail (unused when B % 4 == 0)
        for (long long s = s0; s < B; s++) {
            float xx0 = x[s * 3], xx1 = x[s * 3 + 1];
            float cc0, ss0, cc1, ss1;
            __sincosf(xx0, &ss0, &cc0);
            __sincosf(xx1, &ss1, &cc1);
            float o0 = bias0, o1 = bias1;
            for (int j = 0; j < NHID; j++) {
                const float* K = &sd[j * 24];
                float g = K[0] + K[2]*cc1 + K[4]*ss1 + K[6]*cc0
                        + K[8]*cc0*cc1 + K[10]*cc0*ss1
                        + K[12]*ss0 + K[14]*ss0*cc1 + K[16]*ss0*ss1;
                float h = fmaxf(g, 0.f);
                o0 += h * K[18];
                o1 += h * K[20];
            }
            out[s * 2]     = o0;
            out[s * 2 + 1] = o1;
        }
    }
}

extern "C" void kernel_launch(void* const* d_in, const int* in_sizes, int n_in,
                              void* d_out, int out_size)
{
    const float* x     = (const float*)d_in[0];
    const float* theta = (const float*)d_in[1];
    const float* W1    = (const float*)d_in[2];
    const float* b1    = (const float*)d_in[3];
    const float* W2    = (const float*)d_in[4];
    const float* b2    = (const float*)d_in[5];
    int B = in_sizes[0] / 3;

    setup_kernel<<<1, 32>>>(theta, W1, b1, W2);

    int nthreads = (B + 3) / 4;
    int nblocks  = (nthreads + 255) / 256;
    qmlp_kernel<<<nblocks, 256>>>(x, b2, (float*)d_out, B);
}